// round 6
// baseline (speedup 1.0000x reference)
#include <cuda_runtime.h>
#include <cuda_bf16.h>

// Sinkhorn OT, B=1024, N=M=256, 100 iters. One CTA (512 threads) per batch.
// K = exp(-C/eps) bf16. Each thread holds an 8x16 tile of K in REGISTERS
// (64 words); both matvecs run register-resident. Shared memory carries only
// vectors + partials, with conflict-free layouts:
//   ps1[t*16+i] == rg*256 + col  (CF stores and CF column reduction)
//   v2 stride-17 copy            (CF strided v loads in loop2)
//   ps2 stride-18 rows           (CF stores, <=2-way reduction)

#define B_TOT   1024
#define ITERS   100
#define INV_EPS 10.0f
#define EPS_DIV 1e-8f

#define ROWW_W  132                        // words per padded K row
#define OFF_A   (256*ROWW_W*4)             // 135168
#define OFF_B   (OFF_A + 1024)
#define OFF_U   (OFF_B + 1024)
#define OFF_V   (OFF_U + 1024)
#define OFF_V2  (OFF_V + 1024)             // 272 floats (17*16), pad to 1152
#define OFF_PS1 (OFF_V2 + 1152)            // 8192 floats = 32768 B
#define OFF_PS2 (OFF_PS1 + 32768)          // 256*18 floats = 18432 B
#define SMEM_BYTES (OFF_PS2 + 18432)       // 191616

__device__ float g_cost[B_TOT];

__device__ __forceinline__ float bflo(unsigned int p) { return __uint_as_float(p << 16); }
__device__ __forceinline__ float bfhi(unsigned int p) { return __uint_as_float(p & 0xffff0000u); }

extern __shared__ unsigned char smem_raw[];

__global__ __launch_bounds__(512, 1)
void sinkhorn_kernel(const float* __restrict__ C,
                     const float* __restrict__ mass_pred,
                     const float* __restrict__ mass_target)
{
    unsigned short* sK = (unsigned short*)smem_raw;            // 256 x 264 bf16
    const unsigned int* sKw = (const unsigned int*)smem_raw;   // word view
    float* s_a   = (float*)(smem_raw + OFF_A);
    float* s_b   = (float*)(smem_raw + OFF_B);
    float* s_u   = (float*)(smem_raw + OFF_U);
    float* s_v   = (float*)(smem_raw + OFF_V);
    float* s_v2  = (float*)(smem_raw + OFF_V2);
    float* s_ps1 = (float*)(smem_raw + OFF_PS1);
    float* s_ps2 = (float*)(smem_raw + OFF_PS2);

    const int b = blockIdx.x;
    const int t = threadIdx.x;
    const float* __restrict__ Cb = C + (size_t)b * 65536;

    // ---------- Build K = exp(-C/eps) (bf16, padded rows) ----------
    #pragma unroll 4
    for (int k = 0; k < 32; k++) {
        int idx4 = k * 512 + t;
        float4 c = ((const float4*)Cb)[idx4];
        int lin = idx4 << 2;
        int n = lin >> 8;
        int m = lin & 255;
        __nv_bfloat162 p0 = __floats2bfloat162_rn(__expf(-c.x * INV_EPS),
                                                  __expf(-c.y * INV_EPS));
        __nv_bfloat162 p1 = __floats2bfloat162_rn(__expf(-c.z * INV_EPS),
                                                  __expf(-c.w * INV_EPS));
        *(__nv_bfloat162*)&sK[n * (ROWW_W*2) + m]     = p0;
        *(__nv_bfloat162*)&sK[n * (ROWW_W*2) + m + 2] = p1;
    }

    // ---------- Normalize masses (threads 0-255), ps1 as scratch ----------
    if (t < 256) {
        float mpv = mass_pred[b * 256 + t];
        float mtv = mass_target[b * 256 + t];
        float sa = mpv, sb = mtv;
        #pragma unroll
        for (int o = 16; o; o >>= 1) {
            sa += __shfl_xor_sync(0xffffffffu, sa, o);
            sb += __shfl_xor_sync(0xffffffffu, sb, o);
        }
        if ((t & 31) == 0) { s_ps1[t >> 5] = sa; s_ps1[8 + (t >> 5)] = sb; }
        s_ps1[64 + t]  = mpv;
        s_ps1[320 + t] = mtv;
    }
    __syncthreads();
    if (t < 256) {
        float suma = 0.f, sumb = 0.f;
        #pragma unroll
        for (int w = 0; w < 8; w++) { suma += s_ps1[w]; sumb += s_ps1[8 + w]; }
        s_a[t] = s_ps1[64 + t]  / (suma + EPS_DIV);
        s_b[t] = s_ps1[320 + t] / (sumb + EPS_DIV);
        s_u[t] = 1.0f;
    }
    __syncthreads();

    // ---------- Load this thread's 8x16 K tile into registers ----------
    const int rg = t >> 4;     // row group: rows 8rg..8rg+7
    const int cg = t & 15;     // col group: cols 16cg..16cg+15 (words 8cg..8cg+7)
    uint4 kr[16];
    #pragma unroll
    for (int r = 0; r < 8; r++) {
        kr[2*r]   = *(const uint4*)&sKw[(rg*8 + r) * ROWW_W + cg*8];
        kr[2*r+1] = *(const uint4*)&sKw[(rg*8 + r) * ROWW_W + cg*8 + 4];
    }

    // ---------- 100 Sinkhorn iterations ----------
    for (int it = 0; it < ITERS; it++) {
        // ===== loop1: Kt_u partials (16 cols over 8 own rows) =====
        float4 ua = *(const float4*)&s_u[rg*8];
        float4 ub = *(const float4*)&s_u[rg*8 + 4];
        float ur[8] = {ua.x, ua.y, ua.z, ua.w, ub.x, ub.y, ub.z, ub.w};
        float acc[16];
        #pragma unroll
        for (int i = 0; i < 16; i++) acc[i] = 0.f;
        #pragma unroll
        for (int r = 0; r < 8; r++) {
            uint4 w0 = kr[2*r], w1 = kr[2*r+1];
            float u_r = ur[r];
            acc[0]  += bflo(w0.x) * u_r;  acc[1]  += bfhi(w0.x) * u_r;
            acc[2]  += bflo(w0.y) * u_r;  acc[3]  += bfhi(w0.y) * u_r;
            acc[4]  += bflo(w0.z) * u_r;  acc[5]  += bfhi(w0.z) * u_r;
            acc[6]  += bflo(w0.w) * u_r;  acc[7]  += bfhi(w0.w) * u_r;
            acc[8]  += bflo(w1.x) * u_r;  acc[9]  += bfhi(w1.x) * u_r;
            acc[10] += bflo(w1.y) * u_r;  acc[11] += bfhi(w1.y) * u_r;
            acc[12] += bflo(w1.z) * u_r;  acc[13] += bfhi(w1.z) * u_r;
            acc[14] += bflo(w1.w) * u_r;  acc[15] += bfhi(w1.w) * u_r;
        }
        // ps1[t*16+i] == rg*256 + (16cg+i): conflict-free store & reduction
        #pragma unroll
        for (int q = 0; q < 4; q++)
            *(float4*)&s_ps1[t*16 + 4*q] =
                make_float4(acc[4*q], acc[4*q+1], acc[4*q+2], acc[4*q+3]);
        __syncthreads();

        if (t < 256) {
            float kt = 0.f;
            #pragma unroll
            for (int g = 0; g < 32; g++) kt += s_ps1[g*256 + t];
            float vv = __fdividef(s_b[t], kt + EPS_DIV);
            s_v[t] = vv;
            s_v2[17*(t >> 4) + (t & 15)] = vv;   // strided copy for loop2
        }
        __syncthreads();

        // ===== loop2: K_v partials (8 own rows over 16 own cols) =====
        float vr[16];
        #pragma unroll
        for (int i = 0; i < 16; i++) vr[i] = s_v2[17*cg + i];
        #pragma unroll
        for (int r = 0; r < 8; r++) {
            uint4 w0 = kr[2*r], w1 = kr[2*r+1];
            float s =
                bflo(w0.x)*vr[0]  + bfhi(w0.x)*vr[1]  +
                bflo(w0.y)*vr[2]  + bfhi(w0.y)*vr[3]  +
                bflo(w0.z)*vr[4]  + bfhi(w0.z)*vr[5]  +
                bflo(w0.w)*vr[6]  + bfhi(w0.w)*vr[7]  +
                bflo(w1.x)*vr[8]  + bfhi(w1.x)*vr[9]  +
                bflo(w1.y)*vr[10] + bfhi(w1.y)*vr[11] +
                bflo(w1.z)*vr[12] + bfhi(w1.z)*vr[13] +
                bflo(w1.w)*vr[14] + bfhi(w1.w)*vr[15];
            s_ps2[(rg*8 + r)*18 + cg] = s;      // CF: halves hit disjoint banks
        }
        __syncthreads();

        if (t < 256) {
            float kv = 0.f;
            #pragma unroll
            for (int p = 0; p < 8; p++) {
                float2 x = *(const float2*)&s_ps2[t*18 + 2*p];
                kv += x.x + x.y;
            }
            s_u[t] = __fdividef(s_a[t], kv + EPS_DIV);
        }
        __syncthreads();
    }

    // ---------- ot_cost[b] = sum u[n] K[n,m] v[m] C[n,m] ----------
    float accf = 0.f;
    #pragma unroll 4
    for (int k = 0; k < 32; k++) {
        int idx4 = k * 512 + t;
        float4 c = ((const float4*)Cb)[idx4];
        int lin = idx4 << 2;
        int n = lin >> 8;
        int m = lin & 255;
        uint2 q = *(const uint2*)&sKw[n * ROWW_W + (m >> 1)];
        float un = s_u[n];
        float4 vv = *(const float4*)&s_v[m];
        accf += un * (bflo(q.x) * vv.x * c.x + bfhi(q.x) * vv.y * c.y
                    + bflo(q.y) * vv.z * c.z + bfhi(q.y) * vv.w * c.w);
    }
    #pragma unroll
    for (int o = 16; o; o >>= 1) accf += __shfl_xor_sync(0xffffffffu, accf, o);
    __syncthreads();
    if ((t & 31) == 0) s_ps1[t >> 5] = accf;
    __syncthreads();
    if (t == 0) {
        float s = 0.f;
        #pragma unroll
        for (int w = 0; w < 16; w++) s += s_ps1[w];
        g_cost[b] = s;
    }
}

__global__ void reduce_kernel(float* __restrict__ out)
{
    __shared__ float sm[8];
    int t = threadIdx.x;
    float s = 0.f;
    #pragma unroll
    for (int i = t; i < B_TOT; i += 256) s += g_cost[i];
    #pragma unroll
    for (int o = 16; o; o >>= 1) s += __shfl_xor_sync(0xffffffffu, s, o);
    if ((t & 31) == 0) sm[t >> 5] = s;
    __syncthreads();
    if (t == 0) {
        float tot = 0.f;
        #pragma unroll
        for (int w = 0; w < 8; w++) tot += sm[w];
        out[0] = tot * (1.0f / B_TOT);
    }
}

extern "C" void kernel_launch(void* const* d_in, const int* in_sizes, int n_in,
                              void* d_out, int out_size)
{
    const float* C  = (const float*)d_in[0];
    const float* mp = (const float*)d_in[1];
    const float* mt = (const float*)d_in[2];
    float* out = (float*)d_out;

    cudaFuncSetAttribute(sinkhorn_kernel,
                         cudaFuncAttributeMaxDynamicSharedMemorySize, SMEM_BYTES);

    sinkhorn_kernel<<<B_TOT, 512, SMEM_BYTES>>>(C, mp, mt);
    reduce_kernel<<<1, 256>>>(out);
}

// round 7
// speedup vs baseline: 1.4759x; 1.4759x over previous
#include <cuda_runtime.h>
#include <cuda_bf16.h>
#include <cstdint>

// Sinkhorn OT, B=1024, N=M=256, 100 iters. One CTA (512 threads) per batch.
// Tensor-core formulation via mma.sync.m16n8k16 (bf16 in, f32 acc):
//   Warp w (wr=w>>2, wc=w&3) owns K block rows 64wr..+64, cols 64wc..+64.
//   Registers hold A-fragments of K^T (64 regs) -> matvec1 (K^T u) register-resident.
//   Matvec2 (K v) uses B-fragments of K^T == contiguous 32-bit words of
//   row-major smem K (conflict-free LDS), A = v broadcast fragments.
// Vectors u,v round through bf16 each iteration; reductions/divides in fp32.

#define B_TOT   1024
#define ITERS   100
#define INV_EPS 10.0f
#define EPS_DIV 1e-8f

#define ROWW_W  132                        // words per padded K row
#define KROW_H  264                        // bf16 per padded K row
#define OFF_A   (256*ROWW_W*4)             // 135168
#define OFF_B   (OFF_A + 1024)
#define OFF_U   (OFF_B + 1024)
#define OFF_V   (OFF_U + 1024)
#define OFF_UBF (OFF_V + 1024)             // bf16[256]
#define OFF_VBF (OFF_UBF + 512)            // bf16[256]
#define OFF_PS  (OFF_VBF + 512)            // float[1024]
#define SMEM_BYTES (OFF_PS + 4096)         // 144640

__device__ float g_cost[B_TOT];

__device__ __forceinline__ float bflo(unsigned int p) { return __uint_as_float(p << 16); }
__device__ __forceinline__ float bfhi(unsigned int p) { return __uint_as_float(p & 0xffff0000u); }

__device__ __forceinline__ void mma16816(float& d0, float& d1, float& d2, float& d3,
                                         uint32_t a0, uint32_t a1, uint32_t a2, uint32_t a3,
                                         uint32_t b0, uint32_t b1) {
    asm volatile("mma.sync.aligned.m16n8k16.row.col.f32.bf16.bf16.f32 "
                 "{%0,%1,%2,%3}, {%4,%5,%6,%7}, {%8,%9}, {%0,%1,%2,%3};"
                 : "+f"(d0), "+f"(d1), "+f"(d2), "+f"(d3)
                 : "r"(a0), "r"(a1), "r"(a2), "r"(a3), "r"(b0), "r"(b1));
}

// pack K[r][c], K[r+1][c] (bf16 bits) into one b32 (lo = row r)
__device__ __forceinline__ uint32_t ld2k(const unsigned short* sK, int r, int c) {
    uint32_t lo = sK[r * KROW_H + c];
    uint32_t hi = sK[(r + 1) * KROW_H + c];
    return lo | (hi << 16);
}

extern __shared__ unsigned char smem_raw[];

__global__ __launch_bounds__(512, 1)
void sinkhorn_kernel(const float* __restrict__ C,
                     const float* __restrict__ mass_pred,
                     const float* __restrict__ mass_target)
{
    unsigned short* sK = (unsigned short*)smem_raw;            // 256 x 264 bf16
    const unsigned int* sKw = (const unsigned int*)smem_raw;   // word view
    float* s_a  = (float*)(smem_raw + OFF_A);
    float* s_b  = (float*)(smem_raw + OFF_B);
    float* s_u  = (float*)(smem_raw + OFF_U);
    float* s_v  = (float*)(smem_raw + OFF_V);
    __nv_bfloat16* s_ubf = (__nv_bfloat16*)(smem_raw + OFF_UBF);
    __nv_bfloat16* s_vbf = (__nv_bfloat16*)(smem_raw + OFF_VBF);
    const uint32_t* ubf_w = (const uint32_t*)(smem_raw + OFF_UBF);
    const uint32_t* vbf_w = (const uint32_t*)(smem_raw + OFF_VBF);
    float* s_ps = (float*)(smem_raw + OFF_PS);

    const int b    = blockIdx.x;
    const int t    = threadIdx.x;
    const int w    = t >> 5;
    const int lane = t & 31;
    const int lq   = lane >> 2;     // 0..7
    const int lr   = lane & 3;      // 0..3
    const int wr   = w >> 2;        // K row-block
    const int wc   = w & 3;         // K col-block
    const float* __restrict__ Cb = C + (size_t)b * 65536;

    // ---------- Build K = exp(-C/eps) (bf16, padded rows) ----------
    #pragma unroll 4
    for (int k = 0; k < 32; k++) {
        int idx4 = k * 512 + t;
        float4 c = ((const float4*)Cb)[idx4];
        int lin = idx4 << 2;
        int n = lin >> 8;
        int m = lin & 255;
        __nv_bfloat162 p0 = __floats2bfloat162_rn(__expf(-c.x * INV_EPS),
                                                  __expf(-c.y * INV_EPS));
        __nv_bfloat162 p1 = __floats2bfloat162_rn(__expf(-c.z * INV_EPS),
                                                  __expf(-c.w * INV_EPS));
        *(__nv_bfloat162*)&sK[n * KROW_H + m]     = p0;
        *(__nv_bfloat162*)&sK[n * KROW_H + m + 2] = p1;
    }

    // ---------- Normalize masses (threads 0-255), s_ps scratch ----------
    if (t < 256) {
        float mpv = mass_pred[b * 256 + t];
        float mtv = mass_target[b * 256 + t];
        float sa = mpv, sb = mtv;
        #pragma unroll
        for (int o = 16; o; o >>= 1) {
            sa += __shfl_xor_sync(0xffffffffu, sa, o);
            sb += __shfl_xor_sync(0xffffffffu, sb, o);
        }
        if ((t & 31) == 0) { s_ps[t >> 5] = sa; s_ps[8 + (t >> 5)] = sb; }
        s_ps[64 + t]  = mpv;
        s_ps[320 + t] = mtv;
    }
    // init u0 = 1 (bf16 0x3F80 pairs)
    if (t < 128) ((uint32_t*)(smem_raw + OFF_UBF))[t] = 0x3F803F80u;
    __syncthreads();
    if (t < 256) {
        float suma = 0.f, sumb = 0.f;
        #pragma unroll
        for (int q = 0; q < 8; q++) { suma += s_ps[q]; sumb += s_ps[8 + q]; }
        s_a[t] = s_ps[64 + t]  / (suma + EPS_DIV);
        s_b[t] = s_ps[320 + t] / (sumb + EPS_DIV);
        s_u[t] = 1.0f;
    }
    __syncthreads();

    // ---------- Load A-fragments of K^T (this warp's 64x64 block) ----------
    // Tile (mt,kt): m = K-col 64wc+16mt.., k = K-row 64wr+16kt..
    uint32_t af[4][4][4];
    #pragma unroll
    for (int mt = 0; mt < 4; mt++) {
        #pragma unroll
        for (int kt = 0; kt < 4; kt++) {
            int mb = 64*wc + 16*mt + lq;      // K column
            int kb = 64*wr + 16*kt + 2*lr;    // K row
            af[mt][kt][0] = ld2k(sK, kb,     mb);
            af[mt][kt][1] = ld2k(sK, kb,     mb + 8);
            af[mt][kt][2] = ld2k(sK, kb + 8, mb);
            af[mt][kt][3] = ld2k(sK, kb + 8, mb + 8);
        }
    }
    __syncthreads();

    // ---------- 100 Sinkhorn iterations ----------
    for (int it = 0; it < ITERS; it++) {
        // ===== matvec1: Kt_u = K^T u  (A-frags in regs, B = u broadcast) =====
        #pragma unroll
        for (int mt = 0; mt < 4; mt++) {
            float d0 = 0.f, d1 = 0.f, d2 = 0.f, d3 = 0.f;
            #pragma unroll
            for (int kt = 0; kt < 4; kt++) {
                uint32_t b0 = ubf_w[32*wr + 8*kt + lr];
                uint32_t b1 = ubf_w[32*wr + 8*kt + lr + 4];
                mma16816(d0, d1, d2, d3,
                         af[mt][kt][0], af[mt][kt][1], af[mt][kt][2], af[mt][kt][3],
                         b0, b1);
            }
            if (lr == 0) {
                s_ps[wr*256 + 64*wc + 16*mt + lq]     = d0;   // row lq
                s_ps[wr*256 + 64*wc + 16*mt + lq + 8] = d2;   // row lq+8
            }
        }
        __syncthreads();

        if (t < 256) {
            float ktu = s_ps[t] + s_ps[256 + t] + s_ps[512 + t] + s_ps[768 + t];
            float vv = __fdividef(s_b[t], ktu + EPS_DIV);
            s_v[t] = vv;
            s_vbf[t] = __float2bfloat16(vv);
        }
        __syncthreads();

        // ===== matvec2: K_v = K v  (A = v broadcast, B = K^T from smem) =====
        uint32_t va0[4], va2[4];
        #pragma unroll
        for (int kt2 = 0; kt2 < 4; kt2++) {
            va0[kt2] = vbf_w[32*wc + 8*kt2 + lr];        // cols 2lr,2lr+1
            va2[kt2] = vbf_w[32*wc + 8*kt2 + lr + 4];    // cols +8,+9
        }
        #pragma unroll
        for (int nt = 0; nt < 8; nt++) {
            float d0 = 0.f, d1 = 0.f, d2 = 0.f, d3 = 0.f;
            int rowb = (64*wr + 8*nt + lq) * ROWW_W + 32*wc;
            #pragma unroll
            for (int kt2 = 0; kt2 < 4; kt2++) {
                uint32_t b0 = sKw[rowb + 8*kt2 + lr];
                uint32_t b1 = sKw[rowb + 8*kt2 + lr + 4];
                mma16816(d0, d1, d2, d3,
                         va0[kt2], va0[kt2], va2[kt2], va2[kt2],
                         b0, b1);
            }
            if (lq == 0) {  // rows all equal; cols 2lr, 2lr+1 valid
                *(float2*)&s_ps[wc*256 + 64*wr + 8*nt + 2*lr] = make_float2(d0, d1);
            }
        }
        __syncthreads();

        if (t < 256) {
            float kv = s_ps[t] + s_ps[256 + t] + s_ps[512 + t] + s_ps[768 + t];
            float uu = __fdividef(s_a[t], kv + EPS_DIV);
            s_u[t] = uu;
            s_ubf[t] = __float2bfloat16(uu);
        }
        __syncthreads();
    }

    // ---------- ot_cost[b] = sum u[n] K[n,m] v[m] C[n,m] ----------
    float accf = 0.f;
    #pragma unroll 4
    for (int k = 0; k < 32; k++) {
        int idx4 = k * 512 + t;
        float4 c = ((const float4*)Cb)[idx4];
        int lin = idx4 << 2;
        int n = lin >> 8;
        int m = lin & 255;
        uint2 q = *(const uint2*)&sKw[n * ROWW_W + (m >> 1)];
        float un = s_u[n];
        float4 vv = *(const float4*)&s_v[m];
        accf += un * (bflo(q.x) * vv.x * c.x + bfhi(q.x) * vv.y * c.y
                    + bflo(q.y) * vv.z * c.z + bfhi(q.y) * vv.w * c.w);
    }
    #pragma unroll
    for (int o = 16; o; o >>= 1) accf += __shfl_xor_sync(0xffffffffu, accf, o);
    __syncthreads();
    if ((t & 31) == 0) s_ps[t >> 5] = accf;
    __syncthreads();
    if (t == 0) {
        float s = 0.f;
        #pragma unroll
        for (int q = 0; q < 16; q++) s += s_ps[q];
        g_cost[b] = s;
    }
}

__global__ void reduce_kernel(float* __restrict__ out)
{
    __shared__ float sm[8];
    int t = threadIdx.x;
    float s = 0.f;
    #pragma unroll
    for (int i = t; i < B_TOT; i += 256) s += g_cost[i];
    #pragma unroll
    for (int o = 16; o; o >>= 1) s += __shfl_xor_sync(0xffffffffu, s, o);
    if ((t & 31) == 0) sm[t >> 5] = s;
    __syncthreads();
    if (t == 0) {
        float tot = 0.f;
        #pragma unroll
        for (int q = 0; q < 8; q++) tot += sm[q];
        out[0] = tot * (1.0f / B_TOT);
    }
}

extern "C" void kernel_launch(void* const* d_in, const int* in_sizes, int n_in,
                              void* d_out, int out_size)
{
    const float* C  = (const float*)d_in[0];
    const float* mp = (const float*)d_in[1];
    const float* mt = (const float*)d_in[2];
    float* out = (float*)d_out;

    cudaFuncSetAttribute(sinkhorn_kernel,
                         cudaFuncAttributeMaxDynamicSharedMemorySize, SMEM_BYTES);

    sinkhorn_kernel<<<B_TOT, 512, SMEM_BYTES>>>(C, mp, mt);
    reduce_kernel<<<1, 256>>>(out);
}